// round 3
// baseline (speedup 1.0000x reference)
#include <cuda_runtime.h>
#include <math.h>

#define NN   50000
#define NE   800000
#define ET   (NE + NN)     // edges + self loops
#define FIN  42
#define HIDD 128
#define SCB  ((NN + 255) / 256)   // 196 scan blocks

// ---------------- scratch (device globals; no allocation allowed) -------------
__device__ float g_xn [NN * FIN];
__device__ float g_h  [NN * HIDD];
__device__ float g_cur[NN * HIDD];
__device__ float g_hs [NN];
__device__ float g_hd [NN];
__device__ int   g_deg [NN];
__device__ int   g_off [NN + 1];
__device__ int   g_fill[NN];
__device__ int   g_csr [ET];
__device__ int   g_boff[256];

// ---------------- L1 normalize input ----------------
__global__ void k_xn(const float* __restrict__ x) {
    int w = (blockIdx.x * blockDim.x + threadIdx.x) >> 5;
    int lane = threadIdx.x & 31;
    if (w >= NN) return;
    float s = 0.f;
    for (int j = lane; j < FIN; j += 32) s += fabsf(x[w * FIN + j]);
    #pragma unroll
    for (int o = 16; o; o >>= 1) s += __shfl_xor_sync(0xffffffff, s, o);
    float inv = 1.f / fmaxf(s, 1e-12f);
    for (int j = lane; j < FIN; j += 32) g_xn[w * FIN + j] = x[w * FIN + j] * inv;
}

// ---------------- CSR build (by destination) ----------------
__global__ void k_zero_deg() {
    int i = blockIdx.x * blockDim.x + threadIdx.x;
    if (i < NN) g_deg[i] = 0;
}

__global__ void k_count(const int* __restrict__ ei) {
    int e = blockIdx.x * blockDim.x + threadIdx.x;
    if (e >= ET) return;
    int dst = (e < NE) ? ei[NE + e] : (e - NE);
    atomicAdd(&g_deg[dst], 1);
}

// per-block degree sums
__global__ void k_part() {
    __shared__ int wsum[8];
    int t = threadIdx.x, b = blockIdx.x;
    int node = b * 256 + t;
    int v = (node < NN) ? g_deg[node] : 0;
    #pragma unroll
    for (int o = 16; o; o >>= 1) v += __shfl_xor_sync(0xffffffff, v, o);
    if ((t & 31) == 0) wsum[t >> 5] = v;
    __syncthreads();
    if (t == 0) {
        int s = 0;
        #pragma unroll
        for (int i = 0; i < 8; i++) s += wsum[i];
        g_boff[b] = s;   // temporarily stores block sum
    }
}

// exclusive scan of block sums (one small block)
__global__ void k_scanb() {
    __shared__ int sh[256];
    int t = threadIdx.x;
    int v = (t < SCB) ? g_boff[t] : 0;
    sh[t] = v;
    __syncthreads();
    #pragma unroll
    for (int o = 1; o < 256; o <<= 1) {
        int u = (t >= o) ? sh[t - o] : 0;
        __syncthreads();
        sh[t] += u;
        __syncthreads();
    }
    if (t < SCB) g_boff[t] = sh[t] - v;   // exclusive
    if (t == 255) g_off[NN] = sh[255];    // total
}

// per-block offsets
__global__ void k_off() {
    __shared__ int sh[256];
    int t = threadIdx.x, b = blockIdx.x;
    int node = b * 256 + t;
    int d = (node < NN) ? g_deg[node] : 0;
    sh[t] = d;
    __syncthreads();
    #pragma unroll
    for (int o = 1; o < 256; o <<= 1) {
        int u = (t >= o) ? sh[t - o] : 0;
        __syncthreads();
        sh[t] += u;
        __syncthreads();
    }
    if (node < NN) {
        int off = g_boff[b] + sh[t] - d;
        g_off[node] = off;
        g_fill[node] = off;
    }
}

__global__ void k_scatter(const int* __restrict__ ei) {
    int e = blockIdx.x * blockDim.x + threadIdx.x;
    if (e >= ET) return;
    int src, dst;
    if (e < NE) { src = ei[e]; dst = ei[NE + e]; }
    else        { src = e - NE; dst = e - NE; }
    int pos = atomicAdd(&g_fill[dst], 1);
    g_csr[pos] = src;
}

// ------- SGEMM with fused attention-dot epilogue: C=A@B, hs=C@as, hd=C@ad ----
__global__ void __launch_bounds__(256) k_sgemm(
    const float* __restrict__ A, const float* __restrict__ B,
    float* __restrict__ C,
    const float* __restrict__ as_, const float* __restrict__ ad_,
    int M, int N, int K)
{
    __shared__ float As[8][128];
    __shared__ float Bs[8][128];
    __shared__ float sa[128], sd[128];
    int tid = threadIdx.x;
    int row0 = blockIdx.x * 128;
    int tr = tid >> 4;        // 0..15
    int tc = tid & 15;        // 0..15
    if (tid < 128) {
        sa[tid] = (tid < N) ? as_[tid] : 0.f;
        sd[tid] = (tid < N) ? ad_[tid] : 0.f;
    }
    float acc[8][8];
    #pragma unroll
    for (int i = 0; i < 8; i++)
        #pragma unroll
        for (int j = 0; j < 8; j++) acc[i][j] = 0.f;

    for (int k0 = 0; k0 < K; k0 += 8) {
        #pragma unroll
        for (int l = 0; l < 4; l++) {
            int idx = tid + l * 256;           // 0..1023
            int k = idx & 7, m = idx >> 3;
            int gr = row0 + m, gk = k0 + k;
            As[k][m] = (gr < M && gk < K) ? A[gr * K + gk] : 0.f;
        }
        #pragma unroll
        for (int l = 0; l < 4; l++) {
            int idx = tid + l * 256;
            int n = idx & 127, k = idx >> 7;
            int gk = k0 + k;
            Bs[k][n] = (gk < K && n < N) ? B[gk * N + n] : 0.f;
        }
        __syncthreads();
        #pragma unroll
        for (int kk = 0; kk < 8; kk++) {
            float ar[8], br[8];
            #pragma unroll
            for (int i = 0; i < 8; i++) ar[i] = As[kk][tr * 8 + i];
            #pragma unroll
            for (int j = 0; j < 8; j++) br[j] = Bs[kk][tc * 8 + j];
            #pragma unroll
            for (int i = 0; i < 8; i++)
                #pragma unroll
                for (int j = 0; j < 8; j++) acc[i][j] += ar[i] * br[j];
        }
        __syncthreads();
    }
    // store + fused per-row dots (reduce across the 16 tc threads of a row)
    #pragma unroll
    for (int i = 0; i < 8; i++) {
        int r = row0 + tr * 8 + i;
        float s = 0.f, d = 0.f;
        if (r < M) {
            #pragma unroll
            for (int j = 0; j < 8; j++) {
                int c = tc * 8 + j;
                float v = acc[i][j];
                s += v * sa[c];
                d += v * sd[c];
                if (c < N) C[r * N + c] = v;
            }
        }
        #pragma unroll
        for (int o = 8; o; o >>= 1) {
            s += __shfl_xor_sync(0xffffffff, s, o);
            d += __shfl_xor_sync(0xffffffff, d, o);
        }
        if (tc == 0 && r < M) { g_hs[r] = s; g_hd[r] = d; }
    }
}

// ---------------- softmax-attention aggregation: block per dst node ----------
#define MAXD 1024
__global__ void __launch_bounds__(128) k_agg(
    const float* __restrict__ h, const float* __restrict__ bias,
    float* __restrict__ out, int F)
{
    int node = blockIdx.x;
    int t = threadIdx.x;  // 128
    int lane = t & 31, warp = t >> 5;
    __shared__ int   ssrc[MAXD];
    __shared__ float se  [MAXD];
    __shared__ float red[4];
    __shared__ float redS[4];
    int beg = g_off[node], end = g_off[node + 1];
    int deg = end - beg;
    float hdv = g_hd[node];
    bool cached = (deg <= MAXD);

    // phase 1: logits + block max
    float mymax = -INFINITY;
    if (cached) {
        for (int i = t; i < deg; i += 128) {
            int src = g_csr[beg + i];
            float s = g_hs[src] + hdv;
            float e = (s > 0.f) ? s : 0.2f * s;
            ssrc[i] = src;
            se[i] = e;
            mymax = fmaxf(mymax, e);
        }
    } else {
        for (int i = t; i < deg; i += 128) {
            float s = g_hs[g_csr[beg + i]] + hdv;
            mymax = fmaxf(mymax, (s > 0.f) ? s : 0.2f * s);
        }
    }
    #pragma unroll
    for (int o = 16; o; o >>= 1) mymax = fmaxf(mymax, __shfl_xor_sync(0xffffffff, mymax, o));
    if (lane == 0) red[warp] = mymax;
    __syncthreads();
    float M = fmaxf(fmaxf(red[0], red[1]), fmaxf(red[2], red[3]));

    // phase 2: exp weights + block sum
    float myS = 0.f;
    if (cached) {
        for (int i = t; i < deg; i += 128) {
            float w = expf(se[i] - M);
            se[i] = w;
            myS += w;
        }
    } else {
        for (int i = t; i < deg; i += 128) {
            float s = g_hs[g_csr[beg + i]] + hdv;
            float e = (s > 0.f) ? s : 0.2f * s;
            myS += expf(e - M);
        }
    }
    #pragma unroll
    for (int o = 16; o; o >>= 1) myS += __shfl_xor_sync(0xffffffff, myS, o);
    if (lane == 0) redS[warp] = myS;
    __syncthreads();
    float S = redS[0] + redS[1] + redS[2] + redS[3];
    float invS = 1.f / (S + 1e-16f);

    // phase 3: barrier-free gather accumulation
    float acc = 0.f;
    if (t < F) {
        if (cached) {
            int k = 0;
            for (; k + 4 <= deg; k += 4) {
                float w0 = se[k],     w1 = se[k + 1];
                float w2 = se[k + 2], w3 = se[k + 3];
                const float* r0 = h + (long)ssrc[k]     * F;
                const float* r1 = h + (long)ssrc[k + 1] * F;
                const float* r2 = h + (long)ssrc[k + 2] * F;
                const float* r3 = h + (long)ssrc[k + 3] * F;
                acc += w0 * r0[t] + w1 * r1[t] + w2 * r2[t] + w3 * r3[t];
            }
            for (; k < deg; k++) acc += se[k] * h[(long)ssrc[k] * F + t];
        } else {
            for (int k = 0; k < deg; k++) {
                int src = g_csr[beg + k];
                float s = g_hs[src] + hdv;
                float e = (s > 0.f) ? s : 0.2f * s;
                acc += expf(e - M) * h[(long)src * F + t];
            }
        }
        out[node * F + t] = tanhf(acc * invS + bias[t]);
    }
}

// ---------------- mask MLP + soft-argmax gating (32 nodes per block) ---------
__global__ void __launch_bounds__(128) k_mask(
    float* __restrict__ cur,
    const float* __restrict__ mw1, const float* __restrict__ mb1,
    const float* __restrict__ mw2, const float* __restrict__ mb2,
    const float* __restrict__ mw3, const float* __restrict__ mb3,
    const float* __restrict__ mw4, const float* __restrict__ mb4)
{
    __shared__ float w1[128 * 64];
    __shared__ float w2[64 * 16];
    __shared__ float w3[16 * 16];
    __shared__ float w4[16 * 2];
    __shared__ float bb1[64], bb2[16], bb3[16], bb4[2];
    __shared__ float lat[128], m1[64], m2[16], m3[16];
    __shared__ float sa;
    int t = threadIdx.x;
    for (int i = t; i < 128 * 64; i += 128) w1[i] = mw1[i];
    for (int i = t; i < 64 * 16;  i += 128) w2[i] = mw2[i];
    for (int i = t; i < 16 * 16;  i += 128) w3[i] = mw3[i];
    if (t < 32) w4[t] = mw4[t];
    if (t < 64) bb1[t] = mb1[t];
    if (t < 16) { bb2[t] = mb2[t]; bb3[t] = mb3[t]; }
    if (t < 2)  bb4[t] = mb4[t];
    __syncthreads();

    int n0 = blockIdx.x * 32;
    int n1 = min(n0 + 32, NN);
    for (int n = n0; n < n1; n++) {
        lat[t] = cur[n * 128 + t];
        __syncthreads();
        if (t < 64) {
            float s = bb1[t];
            #pragma unroll 8
            for (int k = 0; k < 128; k++) s += lat[k] * w1[k * 64 + t];
            m1[t] = tanhf(s);
        }
        __syncthreads();
        if (t < 16) {
            float s = bb2[t];
            #pragma unroll
            for (int k = 0; k < 64; k++) s += m1[k] * w2[k * 16 + t];
            m2[t] = tanhf(s);
        }
        __syncthreads();
        if (t < 16) {
            float s = bb3[t];
            #pragma unroll
            for (int k = 0; k < 16; k++) s += m2[k] * w3[k * 16 + t];
            m3[t] = tanhf(s);
        }
        __syncthreads();
        if (t == 0) {
            float o0 = bb4[0], o1 = bb4[1];
            #pragma unroll
            for (int k = 0; k < 16; k++) {
                o0 += m3[k] * w4[k * 2];
                o1 += m3[k] * w4[k * 2 + 1];
            }
            float mx = fmaxf(o0, o1);
            float e0 = expf(o0 - mx), e1 = expf(o1 - mx);
            sa = e1 / (e0 + e1);           // soft argmax = p(class 1)
        }
        __syncthreads();
        cur[n * 128 + t] = lat[t] * sa;
    }
}

// ---------------- orchestration ----------------
extern "C" void kernel_launch(void* const* d_in, const int* in_sizes, int n_in,
                              void* d_out, int out_size)
{
    const float* x   = (const float*)d_in[0];
    const int*   ei  = (const int*)  d_in[1];
    // d_in[2] = batch (unused), d_in[3] = epoch (unused)
    const float* W1  = (const float*)d_in[4];
    const float* a1s = (const float*)d_in[5];
    const float* a1d = (const float*)d_in[6];
    const float* b1  = (const float*)d_in[7];
    const float* Wm  = (const float*)d_in[8];
    const float* ams = (const float*)d_in[9];
    const float* amd = (const float*)d_in[10];
    const float* bm  = (const float*)d_in[11];
    const float* W8  = (const float*)d_in[12];
    const float* a8s = (const float*)d_in[13];
    const float* a8d = (const float*)d_in[14];
    const float* b8  = (const float*)d_in[15];
    const float* mw1 = (const float*)d_in[16];
    const float* mb1 = (const float*)d_in[17];
    const float* mw2 = (const float*)d_in[18];
    const float* mb2 = (const float*)d_in[19];
    const float* mw3 = (const float*)d_in[20];
    const float* mb3 = (const float*)d_in[21];
    const float* mw4 = (const float*)d_in[22];
    const float* mb4 = (const float*)d_in[23];
    float* outp = (float*)d_out;

    void *pv;
    cudaGetSymbolAddress(&pv, g_xn);   float* p_xn  = (float*)pv;
    cudaGetSymbolAddress(&pv, g_h);    float* p_h   = (float*)pv;
    cudaGetSymbolAddress(&pv, g_cur);  float* p_cur = (float*)pv;

    const int EB = (ET + 255) / 256;
    const int GEMM_B = (NN + 127) / 128;   // 391
    const int WARP8  = (NN + 7) / 8;       // 6250 blocks of 8 warps

    // input normalize + CSR build
    k_xn<<<WARP8, 256>>>(x);
    k_zero_deg<<<(NN + 255) / 256, 256>>>();
    k_count<<<EB, 256>>>(ei);
    k_part<<<SCB, 256>>>();
    k_scanb<<<1, 256>>>();
    k_off<<<SCB, 256>>>();
    k_scatter<<<EB, 256>>>(ei);

    // conv1: 42 -> 128
    k_sgemm<<<GEMM_B, 256>>>(p_xn, W1, p_h, a1s, a1d, NN, HIDD, FIN);
    k_agg<<<NN, 128>>>(p_h, b1, p_cur, HIDD);

    // conv2..conv4
    for (int i = 0; i < 3; i++) {
        k_sgemm<<<GEMM_B, 256>>>(p_cur, Wm + i * HIDD * HIDD, p_h,
                                 ams + i * HIDD, amd + i * HIDD, NN, HIDD, HIDD);
        k_agg<<<NN, 128>>>(p_h, bm + i * HIDD, p_cur, HIDD);
    }

    // mask MLP gating (in place on latent)
    k_mask<<<(NN + 31) / 32, 128>>>(p_cur, mw1, mb1, mw2, mb2, mw3, mb3, mw4, mb4);

    // conv5..conv7
    for (int i = 3; i < 6; i++) {
        k_sgemm<<<GEMM_B, 256>>>(p_cur, Wm + i * HIDD * HIDD, p_h,
                                 ams + i * HIDD, amd + i * HIDD, NN, HIDD, HIDD);
        k_agg<<<NN, 128>>>(p_h, bm + i * HIDD, p_cur, HIDD);
    }

    // conv8: 128 -> 42, writes final output
    k_sgemm<<<GEMM_B, 256>>>(p_cur, W8, p_h, a8s, a8d, NN, FIN, HIDD);
    k_agg<<<NN, 128>>>(p_h, b8, outp, FIN);
}

// round 4
// speedup vs baseline: 1.2930x; 1.2930x over previous
#include <cuda_runtime.h>
#include <math.h>

#define NN   50000
#define NE   800000
#define ET   (NE + NN)     // edges + self loops
#define FIN  42
#define HIDD 128
#define SCB  ((NN + 255) / 256)   // 196 scan blocks

// ---------------- scratch (device globals; no allocation allowed) -------------
__device__ float g_xn [NN * FIN];
__device__ float g_h  [NN * HIDD];
__device__ float g_cur[NN * HIDD];
__device__ float g_hs [NN];
__device__ float g_hd [NN];
__device__ int   g_deg [NN];
__device__ int   g_off [NN + 1];
__device__ int   g_fill[NN];
__device__ int   g_csr [ET];
__device__ int   g_boff[256];

// ---------------- L1 normalize input ----------------
__global__ void k_xn(const float* __restrict__ x) {
    int w = (blockIdx.x * blockDim.x + threadIdx.x) >> 5;
    int lane = threadIdx.x & 31;
    if (w >= NN) return;
    float s = 0.f;
    for (int j = lane; j < FIN; j += 32) s += fabsf(x[w * FIN + j]);
    #pragma unroll
    for (int o = 16; o; o >>= 1) s += __shfl_xor_sync(0xffffffff, s, o);
    float inv = 1.f / fmaxf(s, 1e-12f);
    for (int j = lane; j < FIN; j += 32) g_xn[w * FIN + j] = x[w * FIN + j] * inv;
}

// ---------------- CSR build (by destination) ----------------
__global__ void k_zero_deg() {
    int i = blockIdx.x * blockDim.x + threadIdx.x;
    if (i < NN) g_deg[i] = 0;
}

__global__ void k_count(const int* __restrict__ ei) {
    int e = blockIdx.x * blockDim.x + threadIdx.x;
    if (e >= ET) return;
    int dst = (e < NE) ? ei[NE + e] : (e - NE);
    atomicAdd(&g_deg[dst], 1);
}

__global__ void k_part() {
    __shared__ int wsum[8];
    int t = threadIdx.x, b = blockIdx.x;
    int node = b * 256 + t;
    int v = (node < NN) ? g_deg[node] : 0;
    #pragma unroll
    for (int o = 16; o; o >>= 1) v += __shfl_xor_sync(0xffffffff, v, o);
    if ((t & 31) == 0) wsum[t >> 5] = v;
    __syncthreads();
    if (t == 0) {
        int s = 0;
        #pragma unroll
        for (int i = 0; i < 8; i++) s += wsum[i];
        g_boff[b] = s;
    }
}

__global__ void k_scanb() {
    __shared__ int sh[256];
    int t = threadIdx.x;
    int v = (t < SCB) ? g_boff[t] : 0;
    sh[t] = v;
    __syncthreads();
    #pragma unroll
    for (int o = 1; o < 256; o <<= 1) {
        int u = (t >= o) ? sh[t - o] : 0;
        __syncthreads();
        sh[t] += u;
        __syncthreads();
    }
    if (t < SCB) g_boff[t] = sh[t] - v;
    if (t == 255) g_off[NN] = sh[255];
}

__global__ void k_off() {
    __shared__ int sh[256];
    int t = threadIdx.x, b = blockIdx.x;
    int node = b * 256 + t;
    int d = (node < NN) ? g_deg[node] : 0;
    sh[t] = d;
    __syncthreads();
    #pragma unroll
    for (int o = 1; o < 256; o <<= 1) {
        int u = (t >= o) ? sh[t - o] : 0;
        __syncthreads();
        sh[t] += u;
        __syncthreads();
    }
    if (node < NN) {
        int off = g_boff[b] + sh[t] - d;
        g_off[node] = off;
        g_fill[node] = off;
    }
}

__global__ void k_scatter(const int* __restrict__ ei) {
    int e = blockIdx.x * blockDim.x + threadIdx.x;
    if (e >= ET) return;
    int src, dst;
    if (e < NE) { src = ei[e]; dst = ei[NE + e]; }
    else        { src = e - NE; dst = e - NE; }
    int pos = atomicAdd(&g_fill[dst], 1);
    g_csr[pos] = src;
}

// ------- SGEMM with fused attention-dot epilogue: C=A@B, hs=C@as, hd=C@ad ----
__global__ void __launch_bounds__(256) k_sgemm(
    const float* __restrict__ A, const float* __restrict__ B,
    float* __restrict__ C,
    const float* __restrict__ as_, const float* __restrict__ ad_,
    int M, int N, int K)
{
    __shared__ float As[8][132];   // padded: conflict-free strided writes
    __shared__ float Bs[8][128];
    __shared__ float sa[128], sd[128];
    int tid = threadIdx.x;
    int row0 = blockIdx.x * 128;
    int tr = tid >> 4;        // 0..15
    int tc = tid & 15;        // 0..15
    if (tid < 128) {
        sa[tid] = (tid < N) ? as_[tid] : 0.f;
        sd[tid] = (tid < N) ? ad_[tid] : 0.f;
    }
    float acc[8][8];
    #pragma unroll
    for (int i = 0; i < 8; i++)
        #pragma unroll
        for (int j = 0; j < 8; j++) acc[i][j] = 0.f;

    for (int k0 = 0; k0 < K; k0 += 8) {
        #pragma unroll
        for (int l = 0; l < 4; l++) {
            int idx = tid + l * 256;           // 0..1023
            int k = idx & 7, m = idx >> 3;
            int gr = row0 + m, gk = k0 + k;
            As[k][m] = (gr < M && gk < K) ? A[gr * K + gk] : 0.f;
        }
        #pragma unroll
        for (int l = 0; l < 4; l++) {
            int idx = tid + l * 256;
            int n = idx & 127, k = idx >> 7;
            int gk = k0 + k;
            Bs[k][n] = (gk < K && n < N) ? B[gk * N + n] : 0.f;
        }
        __syncthreads();
        #pragma unroll
        for (int kk = 0; kk < 8; kk++) {
            float ar[8], br[8];
            #pragma unroll
            for (int i = 0; i < 8; i++) ar[i] = As[kk][tr * 8 + i];
            #pragma unroll
            for (int j = 0; j < 8; j++) br[j] = Bs[kk][tc * 8 + j];
            #pragma unroll
            for (int i = 0; i < 8; i++)
                #pragma unroll
                for (int j = 0; j < 8; j++) acc[i][j] += ar[i] * br[j];
        }
        __syncthreads();
    }
    #pragma unroll
    for (int i = 0; i < 8; i++) {
        int r = row0 + tr * 8 + i;
        float s = 0.f, d = 0.f;
        if (r < M) {
            #pragma unroll
            for (int j = 0; j < 8; j++) {
                int c = tc * 8 + j;
                float v = acc[i][j];
                s += v * sa[c];
                d += v * sd[c];
                if (c < N) C[r * N + c] = v;
            }
        }
        #pragma unroll
        for (int o = 8; o; o >>= 1) {
            s += __shfl_xor_sync(0xffffffff, s, o);
            d += __shfl_xor_sync(0xffffffff, d, o);
        }
        if (tc == 0 && r < M) { g_hs[r] = s; g_hd[r] = d; }
    }
}

// ------------- warp-per-node softmax aggregation (no barriers) ---------------
template<int F>
__global__ void __launch_bounds__(256) k_aggw(
    const float* __restrict__ h, const float* __restrict__ bias,
    float* __restrict__ out)
{
    int w = (blockIdx.x * blockDim.x + threadIdx.x) >> 5;
    int lane = threadIdx.x & 31;
    if (w >= NN) return;
    int beg = g_off[w], end = g_off[w + 1];
    int deg = end - beg;
    int nk = (deg + 31) >> 5;
    float hdv = g_hd[w];

    // pass 1: logits (cached in regs for deg<=128) + warp max
    float cW[4]; int cS[4];
    float mymax = -INFINITY;
    for (int c = 0; c < nk; c++) {
        int i = (c << 5) + lane;
        float e = -INFINITY; int s = 0;
        if (i < deg) {
            s = g_csr[beg + i];
            float z = g_hs[s] + hdv;
            e = (z > 0.f) ? z : 0.2f * z;
        }
        if (c < 4) { cS[c] = s; cW[c] = e; }
        mymax = fmaxf(mymax, e);
    }
    #pragma unroll
    for (int o = 16; o; o >>= 1) mymax = fmaxf(mymax, __shfl_xor_sync(0xffffffff, mymax, o));
    float M = mymax;

    // pass 2: exp weights + warp sum
    float myS = 0.f;
    for (int c = 0; c < nk; c++) {
        float e;
        if (c < 4) e = cW[c];
        else {
            int i = (c << 5) + lane;
            e = -INFINITY;
            if (i < deg) {
                float z = g_hs[g_csr[beg + i]] + hdv;
                e = (z > 0.f) ? z : 0.2f * z;
            }
        }
        float wgt = __expf(e - M);     // exp(-inf)=0 for inactive lanes
        if (c < 4) cW[c] = wgt;
        myS += wgt;
    }
    #pragma unroll
    for (int o = 16; o; o >>= 1) myS += __shfl_xor_sync(0xffffffff, myS, o);
    float invS = 1.f / (myS + 1e-16f);

    // pass 3: gather (float4 per lane for F=128)
    if constexpr (F == 128) {
        const float4* h4 = (const float4*)h;
        float4 acc = make_float4(0.f, 0.f, 0.f, 0.f);
        for (int c = 0; c < nk; c++) {
            int cnt = min(32, deg - (c << 5));
            int s; float wgt;
            if (c < 4) { s = cS[c]; wgt = cW[c]; }
            else {
                int i = (c << 5) + lane;
                s = 0; wgt = 0.f;
                if (i < deg) {
                    s = g_csr[beg + i];
                    float z = g_hs[s] + hdv;
                    float e = (z > 0.f) ? z : 0.2f * z;
                    wgt = __expf(e - M);
                }
            }
            int k = 0;
            for (; k + 4 <= cnt; k += 4) {
                int   s0 = __shfl_sync(0xffffffff, s, k);
                int   s1 = __shfl_sync(0xffffffff, s, k + 1);
                int   s2 = __shfl_sync(0xffffffff, s, k + 2);
                int   s3 = __shfl_sync(0xffffffff, s, k + 3);
                float w0 = __shfl_sync(0xffffffff, wgt, k);
                float w1 = __shfl_sync(0xffffffff, wgt, k + 1);
                float w2 = __shfl_sync(0xffffffff, wgt, k + 2);
                float w3 = __shfl_sync(0xffffffff, wgt, k + 3);
                float4 v0 = h4[s0 * 32 + lane];
                float4 v1 = h4[s1 * 32 + lane];
                float4 v2 = h4[s2 * 32 + lane];
                float4 v3 = h4[s3 * 32 + lane];
                acc.x += w0 * v0.x + w1 * v1.x + w2 * v2.x + w3 * v3.x;
                acc.y += w0 * v0.y + w1 * v1.y + w2 * v2.y + w3 * v3.y;
                acc.z += w0 * v0.z + w1 * v1.z + w2 * v2.z + w3 * v3.z;
                acc.w += w0 * v0.w + w1 * v1.w + w2 * v2.w + w3 * v3.w;
            }
            for (; k < cnt; k++) {
                int   sk = __shfl_sync(0xffffffff, s, k);
                float wk = __shfl_sync(0xffffffff, wgt, k);
                float4 v = h4[sk * 32 + lane];
                acc.x += wk * v.x; acc.y += wk * v.y;
                acc.z += wk * v.z; acc.w += wk * v.w;
            }
        }
        const float4* b4 = (const float4*)bias;
        float4 bb = b4[lane];
        float4 o;
        o.x = tanhf(acc.x * invS + bb.x);
        o.y = tanhf(acc.y * invS + bb.y);
        o.z = tanhf(acc.z * invS + bb.z);
        o.w = tanhf(acc.w * invS + bb.w);
        ((float4*)out)[w * 32 + lane] = o;
    } else {
        // generic small F (42): 2 features per lane
        float a0 = 0.f, a1 = 0.f;
        int j0 = lane, j1 = lane + 32;
        for (int c = 0; c < nk; c++) {
            int cnt = min(32, deg - (c << 5));
            int s; float wgt;
            if (c < 4) { s = cS[c]; wgt = cW[c]; }
            else {
                int i = (c << 5) + lane;
                s = 0; wgt = 0.f;
                if (i < deg) {
                    s = g_csr[beg + i];
                    float z = g_hs[s] + hdv;
                    float e = (z > 0.f) ? z : 0.2f * z;
                    wgt = __expf(e - M);
                }
            }
            for (int k = 0; k < cnt; k++) {
                int   sk = __shfl_sync(0xffffffff, s, k);
                float wk = __shfl_sync(0xffffffff, wgt, k);
                const float* row = h + (long)sk * F;
                a0 += wk * row[j0];
                if (j1 < F) a1 += wk * row[j1];
            }
        }
        out[(long)w * F + j0] = tanhf(a0 * invS + bias[j0]);
        if (j1 < F) out[(long)w * F + j1] = tanhf(a1 * invS + bias[j1]);
    }
}

// ---------------- mask MLP + soft-argmax gating (32 nodes per block) ---------
__global__ void __launch_bounds__(128) k_mask(
    float* __restrict__ cur,
    const float* __restrict__ mw1, const float* __restrict__ mb1,
    const float* __restrict__ mw2, const float* __restrict__ mb2,
    const float* __restrict__ mw3, const float* __restrict__ mb3,
    const float* __restrict__ mw4, const float* __restrict__ mb4)
{
    __shared__ float w1[128 * 64];
    __shared__ float w2[64 * 16];
    __shared__ float w3[16 * 16];
    __shared__ float w4[16 * 2];
    __shared__ float bb1[64], bb2[16], bb3[16], bb4[2];
    __shared__ float lat[128], m1[64], m2[16], m3[16];
    __shared__ float sa;
    int t = threadIdx.x;
    for (int i = t; i < 128 * 64; i += 128) w1[i] = mw1[i];
    for (int i = t; i < 64 * 16;  i += 128) w2[i] = mw2[i];
    for (int i = t; i < 16 * 16;  i += 128) w3[i] = mw3[i];
    if (t < 32) w4[t] = mw4[t];
    if (t < 64) bb1[t] = mb1[t];
    if (t < 16) { bb2[t] = mb2[t]; bb3[t] = mb3[t]; }
    if (t < 2)  bb4[t] = mb4[t];
    __syncthreads();

    int n0 = blockIdx.x * 32;
    int n1 = min(n0 + 32, NN);
    for (int n = n0; n < n1; n++) {
        lat[t] = cur[n * 128 + t];
        __syncthreads();
        if (t < 64) {
            float s = bb1[t];
            #pragma unroll 8
            for (int k = 0; k < 128; k++) s += lat[k] * w1[k * 64 + t];
            m1[t] = tanhf(s);
        }
        __syncthreads();
        if (t < 16) {
            float s = bb2[t];
            #pragma unroll
            for (int k = 0; k < 64; k++) s += m1[k] * w2[k * 16 + t];
            m2[t] = tanhf(s);
        }
        __syncthreads();
        if (t < 16) {
            float s = bb3[t];
            #pragma unroll
            for (int k = 0; k < 16; k++) s += m2[k] * w3[k * 16 + t];
            m3[t] = tanhf(s);
        }
        __syncthreads();
        if (t == 0) {
            float o0 = bb4[0], o1 = bb4[1];
            #pragma unroll
            for (int k = 0; k < 16; k++) {
                o0 += m3[k] * w4[k * 2];
                o1 += m3[k] * w4[k * 2 + 1];
            }
            float mx = fmaxf(o0, o1);
            float e0 = expf(o0 - mx), e1 = expf(o1 - mx);
            sa = e1 / (e0 + e1);
        }
        __syncthreads();
        cur[n * 128 + t] = lat[t] * sa;
    }
}

// ---------------- orchestration ----------------
extern "C" void kernel_launch(void* const* d_in, const int* in_sizes, int n_in,
                              void* d_out, int out_size)
{
    const float* x   = (const float*)d_in[0];
    const int*   ei  = (const int*)  d_in[1];
    const float* W1  = (const float*)d_in[4];
    const float* a1s = (const float*)d_in[5];
    const float* a1d = (const float*)d_in[6];
    const float* b1  = (const float*)d_in[7];
    const float* Wm  = (const float*)d_in[8];
    const float* ams = (const float*)d_in[9];
    const float* amd = (const float*)d_in[10];
    const float* bm  = (const float*)d_in[11];
    const float* W8  = (const float*)d_in[12];
    const float* a8s = (const float*)d_in[13];
    const float* a8d = (const float*)d_in[14];
    const float* b8  = (const float*)d_in[15];
    const float* mw1 = (const float*)d_in[16];
    const float* mb1 = (const float*)d_in[17];
    const float* mw2 = (const float*)d_in[18];
    const float* mb2 = (const float*)d_in[19];
    const float* mw3 = (const float*)d_in[20];
    const float* mb3 = (const float*)d_in[21];
    const float* mw4 = (const float*)d_in[22];
    const float* mb4 = (const float*)d_in[23];
    float* outp = (float*)d_out;

    void *pv;
    cudaGetSymbolAddress(&pv, g_xn);   float* p_xn  = (float*)pv;
    cudaGetSymbolAddress(&pv, g_h);    float* p_h   = (float*)pv;
    cudaGetSymbolAddress(&pv, g_cur);  float* p_cur = (float*)pv;

    const int EB = (ET + 255) / 256;
    const int GEMM_B = (NN + 127) / 128;       // 391
    const int WARP8  = (NN + 7) / 8;           // 6250 blocks, warp per node
    const int AGG_B  = (NN * 32 + 255) / 256;  // 6250

    // input normalize + CSR build
    k_xn<<<WARP8, 256>>>(x);
    k_zero_deg<<<(NN + 255) / 256, 256>>>();
    k_count<<<EB, 256>>>(ei);
    k_part<<<SCB, 256>>>();
    k_scanb<<<1, 256>>>();
    k_off<<<SCB, 256>>>();
    k_scatter<<<EB, 256>>>(ei);

    // conv1: 42 -> 128
    k_sgemm<<<GEMM_B, 256>>>(p_xn, W1, p_h, a1s, a1d, NN, HIDD, FIN);
    k_aggw<HIDD><<<AGG_B, 256>>>(p_h, b1, p_cur);

    // conv2..conv4
    for (int i = 0; i < 3; i++) {
        k_sgemm<<<GEMM_B, 256>>>(p_cur, Wm + i * HIDD * HIDD, p_h,
                                 ams + i * HIDD, amd + i * HIDD, NN, HIDD, HIDD);
        k_aggw<HIDD><<<AGG_B, 256>>>(p_h, bm + i * HIDD, p_cur);
    }

    // mask MLP gating (in place on latent)
    k_mask<<<(NN + 31) / 32, 128>>>(p_cur, mw1, mb1, mw2, mb2, mw3, mb3, mw4, mb4);

    // conv5..conv7
    for (int i = 3; i < 6; i++) {
        k_sgemm<<<GEMM_B, 256>>>(p_cur, Wm + i * HIDD * HIDD, p_h,
                                 ams + i * HIDD, amd + i * HIDD, NN, HIDD, HIDD);
        k_aggw<HIDD><<<AGG_B, 256>>>(p_h, bm + i * HIDD, p_cur);
    }

    // conv8: 128 -> 42, writes final output
    k_sgemm<<<GEMM_B, 256>>>(p_cur, W8, p_h, a8s, a8d, NN, FIN, HIDD);
    k_aggw<FIN><<<AGG_B, 256>>>(p_h, b8, outp);
}

// round 5
// speedup vs baseline: 1.6697x; 1.2914x over previous
#include <cuda_runtime.h>
#include <math.h>
#include <stdint.h>

#define NN   50000
#define NE   800000
#define ET   (NE + NN)     // edges + self loops
#define FIN  42
#define HIDD 128
#define SCB  ((NN + 255) / 256)   // 196 scan blocks

// ---------------- scratch (device globals; no allocation allowed) -------------
__device__ float g_xn [NN * FIN];
__device__ float g_h  [NN * HIDD];
__device__ float g_cur[NN * HIDD];
__device__ float g_hs [NN];
__device__ float g_hd [NN];
__device__ int   g_deg [NN];
__device__ int   g_off [NN + 1];
__device__ int   g_fill[NN];
__device__ int   g_csr [ET];
__device__ int   g_boff[256];

// ---------------- L1 normalize input ----------------
__global__ void k_xn(const float* __restrict__ x) {
    int w = (blockIdx.x * blockDim.x + threadIdx.x) >> 5;
    int lane = threadIdx.x & 31;
    if (w >= NN) return;
    float s = 0.f;
    for (int j = lane; j < FIN; j += 32) s += fabsf(x[w * FIN + j]);
    #pragma unroll
    for (int o = 16; o; o >>= 1) s += __shfl_xor_sync(0xffffffff, s, o);
    float inv = 1.f / fmaxf(s, 1e-12f);
    for (int j = lane; j < FIN; j += 32) g_xn[w * FIN + j] = x[w * FIN + j] * inv;
}

// ---------------- CSR build (by destination) ----------------
__global__ void k_zero_deg() {
    int i = blockIdx.x * blockDim.x + threadIdx.x;
    if (i < NN) g_deg[i] = 0;
}

__global__ void k_count(const int* __restrict__ ei) {
    int e = blockIdx.x * blockDim.x + threadIdx.x;
    if (e >= ET) return;
    int dst = (e < NE) ? ei[NE + e] : (e - NE);
    atomicAdd(&g_deg[dst], 1);
}

__global__ void k_part() {
    __shared__ int wsum[8];
    int t = threadIdx.x, b = blockIdx.x;
    int node = b * 256 + t;
    int v = (node < NN) ? g_deg[node] : 0;
    #pragma unroll
    for (int o = 16; o; o >>= 1) v += __shfl_xor_sync(0xffffffff, v, o);
    if ((t & 31) == 0) wsum[t >> 5] = v;
    __syncthreads();
    if (t == 0) {
        int s = 0;
        #pragma unroll
        for (int i = 0; i < 8; i++) s += wsum[i];
        g_boff[b] = s;
    }
}

__global__ void k_scanb() {
    __shared__ int sh[256];
    int t = threadIdx.x;
    int v = (t < SCB) ? g_boff[t] : 0;
    sh[t] = v;
    __syncthreads();
    #pragma unroll
    for (int o = 1; o < 256; o <<= 1) {
        int u = (t >= o) ? sh[t - o] : 0;
        __syncthreads();
        sh[t] += u;
        __syncthreads();
    }
    if (t < SCB) g_boff[t] = sh[t] - v;
    if (t == 255) g_off[NN] = sh[255];
}

__global__ void k_off() {
    __shared__ int sh[256];
    int t = threadIdx.x, b = blockIdx.x;
    int node = b * 256 + t;
    int d = (node < NN) ? g_deg[node] : 0;
    sh[t] = d;
    __syncthreads();
    #pragma unroll
    for (int o = 1; o < 256; o <<= 1) {
        int u = (t >= o) ? sh[t - o] : 0;
        __syncthreads();
        sh[t] += u;
        __syncthreads();
    }
    if (node < NN) {
        int off = g_boff[b] + sh[t] - d;
        g_off[node] = off;
        g_fill[node] = off;
    }
}

__global__ void k_scatter(const int* __restrict__ ei) {
    int e = blockIdx.x * blockDim.x + threadIdx.x;
    if (e >= ET) return;
    int src, dst;
    if (e < NE) { src = ei[e]; dst = ei[NE + e]; }
    else        { src = e - NE; dst = e - NE; }
    int pos = atomicAdd(&g_fill[dst], 1);
    g_csr[pos] = src;
}

// ---------------- tf32 tensor-core GEMM with fused dot epilogue ---------------
__device__ __forceinline__ uint32_t f2tf(float f) {
    uint32_t u; asm("cvt.rna.tf32.f32 %0, %1;" : "=r"(u) : "f"(f)); return u;
}
__device__ __forceinline__ void mma_tf32(float c[4],
    uint32_t a0, uint32_t a1, uint32_t a2, uint32_t a3,
    uint32_t b0, uint32_t b1)
{
    asm volatile(
        "mma.sync.aligned.m16n8k8.row.col.f32.tf32.tf32.f32 "
        "{%0,%1,%2,%3}, {%4,%5,%6,%7}, {%8,%9}, {%0,%1,%2,%3};"
        : "+f"(c[0]), "+f"(c[1]), "+f"(c[2]), "+f"(c[3])
        : "r"(a0), "r"(a1), "r"(a2), "r"(a3), "r"(b0), "r"(b1));
}

#define ASTR 36
#define BSTR 136
__global__ void __launch_bounds__(256) k_tgemm(
    const float* __restrict__ A, const float* __restrict__ B,
    float* __restrict__ C,
    const float* __restrict__ as_, const float* __restrict__ ad_,
    int M, int N, int K)
{
    __shared__ uint32_t As[128 * ASTR];
    __shared__ uint32_t Bs[32 * BSTR];
    __shared__ float sa[128], sd[128], sdot[128], ddot[128];
    int tid = threadIdx.x;
    int lane = tid & 31, wid = tid >> 5;
    int wm = wid & 3, wn = wid >> 2;     // warp tile: rows wm*32, cols wn*64
    int row0 = blockIdx.x * 128;
    if (tid < 128) {
        sa[tid] = (tid < N) ? as_[tid] : 0.f;
        sd[tid] = (tid < N) ? ad_[tid] : 0.f;
        sdot[tid] = 0.f; ddot[tid] = 0.f;
    }
    float acc[2][8][4];
    #pragma unroll
    for (int i = 0; i < 2; i++)
        #pragma unroll
        for (int j = 0; j < 8; j++)
            #pragma unroll
            for (int r = 0; r < 4; r++) acc[i][j][r] = 0.f;

    for (int k0 = 0; k0 < K; k0 += 32) {
        // ---- stage A chunk [128 x 32] ----
        if ((K & 3) == 0) {
            #pragma unroll
            for (int l = 0; l < 4; l++) {
                int slot = tid + l * 256;         // 0..1023
                int r = slot >> 3, kg = slot & 7;
                int gr = row0 + r;
                float4 v = make_float4(0.f, 0.f, 0.f, 0.f);
                if (gr < M) v = *(const float4*)&A[(long)gr * K + k0 + kg * 4];
                uint32_t* dst = &As[r * ASTR + kg * 4];
                dst[0] = f2tf(v.x); dst[1] = f2tf(v.y);
                dst[2] = f2tf(v.z); dst[3] = f2tf(v.w);
            }
        } else {
            #pragma unroll
            for (int l = 0; l < 16; l++) {
                int slot = tid + l * 256;         // 0..4095
                int r = slot >> 5, k = slot & 31;
                int gr = row0 + r, gk = k0 + k;
                float v = (gr < M && gk < K) ? A[(long)gr * K + gk] : 0.f;
                As[r * ASTR + k] = f2tf(v);
            }
        }
        // ---- stage B chunk [32 x 128] (zero-padded to 128 cols) ----
        if ((N & 3) == 0) {
            #pragma unroll
            for (int l = 0; l < 4; l++) {
                int slot = tid + l * 256;
                int k = slot >> 5, ng = slot & 31;
                int gk = k0 + k;
                float4 v = make_float4(0.f, 0.f, 0.f, 0.f);
                if (gk < K) v = *(const float4*)&B[(long)gk * N + ng * 4];
                uint32_t* dst = &Bs[k * BSTR + ng * 4];
                dst[0] = f2tf(v.x); dst[1] = f2tf(v.y);
                dst[2] = f2tf(v.z); dst[3] = f2tf(v.w);
            }
        } else {
            #pragma unroll
            for (int l = 0; l < 16; l++) {
                int slot = tid + l * 256;
                int k = slot >> 7, n = slot & 127;
                int gk = k0 + k;
                float v = (gk < K && n < N) ? B[(long)gk * N + n] : 0.f;
                Bs[k * BSTR + n] = f2tf(v);
            }
        }
        __syncthreads();
        // ---- mma over 4 k8-steps ----
        #pragma unroll
        for (int ks = 0; ks < 4; ks++) {
            int kb = ks * 8;
            uint32_t a[2][4];
            #pragma unroll
            for (int fm = 0; fm < 2; fm++) {
                int r = wm * 32 + fm * 16 + (lane >> 2);
                a[fm][0] = As[r * ASTR + kb + (lane & 3)];
                a[fm][1] = As[(r + 8) * ASTR + kb + (lane & 3)];
                a[fm][2] = As[r * ASTR + kb + (lane & 3) + 4];
                a[fm][3] = As[(r + 8) * ASTR + kb + (lane & 3) + 4];
            }
            #pragma unroll
            for (int fn = 0; fn < 8; fn++) {
                int n = wn * 64 + fn * 8 + (lane >> 2);
                uint32_t b0 = Bs[(kb + (lane & 3)) * BSTR + n];
                uint32_t b1 = Bs[(kb + (lane & 3) + 4) * BSTR + n];
                mma_tf32(acc[0][fn], a[0][0], a[0][1], a[0][2], a[0][3], b0, b1);
                mma_tf32(acc[1][fn], a[1][0], a[1][1], a[1][2], a[1][3], b0, b1);
            }
        }
        __syncthreads();
    }

    // ---- epilogue: store C + fused a_s/a_d row dots ----
    #pragma unroll
    for (int fm = 0; fm < 2; fm++) {
        #pragma unroll
        for (int ro = 0; ro < 2; ro++) {
            int rl = wm * 32 + fm * 16 + (lane >> 2) + ro * 8;
            int r = row0 + rl;
            float s = 0.f, d = 0.f;
            #pragma unroll
            for (int fn = 0; fn < 8; fn++) {
                int c = wn * 64 + fn * 8 + (lane & 3) * 2;
                float v0 = acc[fm][fn][ro * 2 + 0];
                float v1 = acc[fm][fn][ro * 2 + 1];
                s += v0 * sa[c] + v1 * sa[c + 1];
                d += v0 * sd[c] + v1 * sd[c + 1];
                if (r < M) {
                    if (c + 1 < N) *(float2*)&C[(long)r * N + c] = make_float2(v0, v1);
                    else if (c < N) C[(long)r * N + c] = v0;
                }
            }
            s += __shfl_xor_sync(0xffffffff, s, 1);
            s += __shfl_xor_sync(0xffffffff, s, 2);
            d += __shfl_xor_sync(0xffffffff, d, 1);
            d += __shfl_xor_sync(0xffffffff, d, 2);
            if ((lane & 3) == 0 && r < M) {
                atomicAdd(&sdot[rl], s);
                atomicAdd(&ddot[rl], d);
            }
        }
    }
    __syncthreads();
    if (tid < 128 && row0 + tid < M) {
        g_hs[row0 + tid] = sdot[tid];
        g_hd[row0 + tid] = ddot[tid];
    }
}

// ------------- warp-per-node softmax aggregation (no barriers) ---------------
template<int F>
__global__ void __launch_bounds__(256) k_aggw(
    const float* __restrict__ h, const float* __restrict__ bias,
    float* __restrict__ out)
{
    int w = (blockIdx.x * blockDim.x + threadIdx.x) >> 5;
    int lane = threadIdx.x & 31;
    if (w >= NN) return;
    int beg = g_off[w], end = g_off[w + 1];
    int deg = end - beg;
    int nk = (deg + 31) >> 5;
    float hdv = g_hd[w];

    float cW[4]; int cS[4];
    float mymax = -INFINITY;
    for (int c = 0; c < nk; c++) {
        int i = (c << 5) + lane;
        float e = -INFINITY; int s = 0;
        if (i < deg) {
            s = g_csr[beg + i];
            float z = g_hs[s] + hdv;
            e = (z > 0.f) ? z : 0.2f * z;
        }
        if (c < 4) { cS[c] = s; cW[c] = e; }
        mymax = fmaxf(mymax, e);
    }
    #pragma unroll
    for (int o = 16; o; o >>= 1) mymax = fmaxf(mymax, __shfl_xor_sync(0xffffffff, mymax, o));
    float M = mymax;

    float myS = 0.f;
    for (int c = 0; c < nk; c++) {
        float e;
        if (c < 4) e = cW[c];
        else {
            int i = (c << 5) + lane;
            e = -INFINITY;
            if (i < deg) {
                float z = g_hs[g_csr[beg + i]] + hdv;
                e = (z > 0.f) ? z : 0.2f * z;
            }
        }
        float wgt = __expf(e - M);
        if (c < 4) cW[c] = wgt;
        myS += wgt;
    }
    #pragma unroll
    for (int o = 16; o; o >>= 1) myS += __shfl_xor_sync(0xffffffff, myS, o);
    float invS = 1.f / (myS + 1e-16f);

    if constexpr (F == 128) {
        const float4* h4 = (const float4*)h;
        float4 acc = make_float4(0.f, 0.f, 0.f, 0.f);
        for (int c = 0; c < nk; c++) {
            int cnt = min(32, deg - (c << 5));
            int s; float wgt;
            if (c < 4) { s = cS[c]; wgt = cW[c]; }
            else {
                int i = (c << 5) + lane;
                s = 0; wgt = 0.f;
                if (i < deg) {
                    s = g_csr[beg + i];
                    float z = g_hs[s] + hdv;
                    float e = (z > 0.f) ? z : 0.2f * z;
                    wgt = __expf(e - M);
                }
            }
            int k = 0;
            for (; k + 4 <= cnt; k += 4) {
                int   s0 = __shfl_sync(0xffffffff, s, k);
                int   s1 = __shfl_sync(0xffffffff, s, k + 1);
                int   s2 = __shfl_sync(0xffffffff, s, k + 2);
                int   s3 = __shfl_sync(0xffffffff, s, k + 3);
                float w0 = __shfl_sync(0xffffffff, wgt, k);
                float w1 = __shfl_sync(0xffffffff, wgt, k + 1);
                float w2 = __shfl_sync(0xffffffff, wgt, k + 2);
                float w3 = __shfl_sync(0xffffffff, wgt, k + 3);
                float4 v0 = h4[s0 * 32 + lane];
                float4 v1 = h4[s1 * 32 + lane];
                float4 v2 = h4[s2 * 32 + lane];
                float4 v3 = h4[s3 * 32 + lane];
                acc.x += w0 * v0.x + w1 * v1.x + w2 * v2.x + w3 * v3.x;
                acc.y += w0 * v0.y + w1 * v1.y + w2 * v2.y + w3 * v3.y;
                acc.z += w0 * v0.z + w1 * v1.z + w2 * v2.z + w3 * v3.z;
                acc.w += w0 * v0.w + w1 * v1.w + w2 * v2.w + w3 * v3.w;
            }
            for (; k < cnt; k++) {
                int   sk = __shfl_sync(0xffffffff, s, k);
                float wk = __shfl_sync(0xffffffff, wgt, k);
                float4 v = h4[sk * 32 + lane];
                acc.x += wk * v.x; acc.y += wk * v.y;
                acc.z += wk * v.z; acc.w += wk * v.w;
            }
        }
        const float4* b4 = (const float4*)bias;
        float4 bb = b4[lane];
        float4 o;
        o.x = tanhf(acc.x * invS + bb.x);
        o.y = tanhf(acc.y * invS + bb.y);
        o.z = tanhf(acc.z * invS + bb.z);
        o.w = tanhf(acc.w * invS + bb.w);
        ((float4*)out)[w * 32 + lane] = o;
    } else {
        float a0 = 0.f, a1 = 0.f;
        int j0 = lane, j1 = lane + 32;
        for (int c = 0; c < nk; c++) {
            int cnt = min(32, deg - (c << 5));
            int s; float wgt;
            if (c < 4) { s = cS[c]; wgt = cW[c]; }
            else {
                int i = (c << 5) + lane;
                s = 0; wgt = 0.f;
                if (i < deg) {
                    s = g_csr[beg + i];
                    float z = g_hs[s] + hdv;
                    float e = (z > 0.f) ? z : 0.2f * z;
                    wgt = __expf(e - M);
                }
            }
            for (int k = 0; k < cnt; k++) {
                int   sk = __shfl_sync(0xffffffff, s, k);
                float wk = __shfl_sync(0xffffffff, wgt, k);
                const float* row = h + (long)sk * F;
                a0 += wk * row[j0];
                if (j1 < F) a1 += wk * row[j1];
            }
        }
        out[(long)w * F + j0] = tanhf(a0 * invS + bias[j0]);
        if (j1 < F) out[(long)w * F + j1] = tanhf(a1 * invS + bias[j1]);
    }
}

// ---------------- mask MLP + soft-argmax gating (32 nodes per block) ---------
__global__ void __launch_bounds__(128) k_mask(
    float* __restrict__ cur,
    const float* __restrict__ mw1, const float* __restrict__ mb1,
    const float* __restrict__ mw2, const float* __restrict__ mb2,
    const float* __restrict__ mw3, const float* __restrict__ mb3,
    const float* __restrict__ mw4, const float* __restrict__ mb4)
{
    __shared__ float w1[128 * 64];
    __shared__ float w2[64 * 16];
    __shared__ float w3[16 * 16];
    __shared__ float w4[16 * 2];
    __shared__ float bb1[64], bb2[16], bb3[16], bb4[2];
    __shared__ float lat[128], m1[64], m2[16], m3[16];
    __shared__ float sa;
    int t = threadIdx.x;
    for (int i = t; i < 128 * 64; i += 128) w1[i] = mw1[i];
    for (int i = t; i < 64 * 16;  i += 128) w2[i] = mw2[i];
    for (int i = t; i < 16 * 16;  i += 128) w3[i] = mw3[i];
    if (t < 32) w4[t] = mw4[t];
    if (t < 64) bb1[t] = mb1[t];
    if (t < 16) { bb2[t] = mb2[t]; bb3[t] = mb3[t]; }
    if (t < 2)  bb4[t] = mb4[t];
    __syncthreads();

    int n0 = blockIdx.x * 32;
    int n1 = min(n0 + 32, NN);
    for (int n = n0; n < n1; n++) {
        lat[t] = cur[n * 128 + t];
        __syncthreads();
        if (t < 64) {
            float s = bb1[t];
            #pragma unroll 8
            for (int k = 0; k < 128; k++) s += lat[k] * w1[k * 64 + t];
            m1[t] = tanhf(s);
        }
        __syncthreads();
        if (t < 16) {
            float s = bb2[t];
            #pragma unroll
            for (int k = 0; k < 64; k++) s += m1[k] * w2[k * 16 + t];
            m2[t] = tanhf(s);
        }
        __syncthreads();
        if (t < 16) {
            float s = bb3[t];
            #pragma unroll
            for (int k = 0; k < 16; k++) s += m2[k] * w3[k * 16 + t];
            m3[t] = tanhf(s);
        }
        __syncthreads();
        if (t == 0) {
            float o0 = bb4[0], o1 = bb4[1];
            #pragma unroll
            for (int k = 0; k < 16; k++) {
                o0 += m3[k] * w4[k * 2];
                o1 += m3[k] * w4[k * 2 + 1];
            }
            float mx = fmaxf(o0, o1);
            float e0 = expf(o0 - mx), e1 = expf(o1 - mx);
            sa = e1 / (e0 + e1);
        }
        __syncthreads();
        cur[n * 128 + t] = lat[t] * sa;
    }
}

// ---------------- orchestration ----------------
extern "C" void kernel_launch(void* const* d_in, const int* in_sizes, int n_in,
                              void* d_out, int out_size)
{
    const float* x   = (const float*)d_in[0];
    const int*   ei  = (const int*)  d_in[1];
    const float* W1  = (const float*)d_in[4];
    const float* a1s = (const float*)d_in[5];
    const float* a1d = (const float*)d_in[6];
    const float* b1  = (const float*)d_in[7];
    const float* Wm  = (const float*)d_in[8];
    const float* ams = (const float*)d_in[9];
    const float* amd = (const float*)d_in[10];
    const float* bm  = (const float*)d_in[11];
    const float* W8  = (const float*)d_in[12];
    const float* a8s = (const float*)d_in[13];
    const float* a8d = (const float*)d_in[14];
    const float* b8  = (const float*)d_in[15];
    const float* mw1 = (const float*)d_in[16];
    const float* mb1 = (const float*)d_in[17];
    const float* mw2 = (const float*)d_in[18];
    const float* mb2 = (const float*)d_in[19];
    const float* mw3 = (const float*)d_in[20];
    const float* mb3 = (const float*)d_in[21];
    const float* mw4 = (const float*)d_in[22];
    const float* mb4 = (const float*)d_in[23];
    float* outp = (float*)d_out;

    void *pv;
    cudaGetSymbolAddress(&pv, g_xn);   float* p_xn  = (float*)pv;
    cudaGetSymbolAddress(&pv, g_h);    float* p_h   = (float*)pv;
    cudaGetSymbolAddress(&pv, g_cur);  float* p_cur = (float*)pv;

    const int EB = (ET + 255) / 256;
    const int GEMM_B = (NN + 127) / 128;       // 391
    const int WARP8  = (NN + 7) / 8;
    const int AGG_B  = (NN * 32 + 255) / 256;  // 6250

    // input normalize + CSR build
    k_xn<<<WARP8, 256>>>(x);
    k_zero_deg<<<(NN + 255) / 256, 256>>>();
    k_count<<<EB, 256>>>(ei);
    k_part<<<SCB, 256>>>();
    k_scanb<<<1, 256>>>();
    k_off<<<SCB, 256>>>();
    k_scatter<<<EB, 256>>>(ei);

    // conv1: 42 -> 128
    k_tgemm<<<GEMM_B, 256>>>(p_xn, W1, p_h, a1s, a1d, NN, HIDD, FIN);
    k_aggw<HIDD><<<AGG_B, 256>>>(p_h, b1, p_cur);

    // conv2..conv4
    for (int i = 0; i < 3; i++) {
        k_tgemm<<<GEMM_B, 256>>>(p_cur, Wm + i * HIDD * HIDD, p_h,
                                 ams + i * HIDD, amd + i * HIDD, NN, HIDD, HIDD);
        k_aggw<HIDD><<<AGG_B, 256>>>(p_h, bm + i * HIDD, p_cur);
    }

    // mask MLP gating (in place on latent)
    k_mask<<<(NN + 31) / 32, 128>>>(p_cur, mw1, mb1, mw2, mb2, mw3, mb3, mw4, mb4);

    // conv5..conv7
    for (int i = 3; i < 6; i++) {
        k_tgemm<<<GEMM_B, 256>>>(p_cur, Wm + i * HIDD * HIDD, p_h,
                                 ams + i * HIDD, amd + i * HIDD, NN, HIDD, HIDD);
        k_aggw<HIDD><<<AGG_B, 256>>>(p_h, bm + i * HIDD, p_cur);
    }

    // conv8: 128 -> 42, writes final output
    k_tgemm<<<GEMM_B, 256>>>(p_cur, W8, p_h, a8s, a8d, NN, FIN, HIDD);
    k_aggw<FIN><<<AGG_B, 256>>>(p_h, b8, outp);
}